// round 11
// baseline (speedup 1.0000x reference)
#include <cuda_runtime.h>
#include <cuda_bf16.h>
#include <math.h>
#include <float.h>

// Problem shape (LG_MGC_2731599200834): B=256, L=576, D=1024, k=24
#define D_DIM  1024
#define NVEC   (D_DIM / 4)        // 256 float4 per row
#define MAX_B  256
#define MAX_L  576
#define MAX_K  64
#define DSPLIT 4                  // tail kernel splits each row into 4 chunks

// Scratch (device global; no allocation allowed).
__device__ float g_sims[MAX_B * MAX_L];

// ---------------------------------------------------------------------------
// Kernel A: one streaming pass over image_feats (604 MB) — DRAM-bound.
// grid = (ceil(L/8), B), block = 256 (8 warps), one warp per token.
// Measured R3: 91.5us @ 84% DRAM (6.66 TB/s) — keep exactly this config.
// Ranking by dot * rsqrt(|t|^2) is order-equivalent to the reference cosine
// (n_i is a positive per-batch scalar; eps clamp inactive at these scales).
// ---------------------------------------------------------------------------
__global__ void __launch_bounds__(256)
sims_kernel(const float* __restrict__ i_feats,
            const float* __restrict__ image_feats,
            int L)
{
    __shared__ float4 s_i[NVEC];    // 4 KB: i_feats row for this batch

    const int b    = blockIdx.y;
    const int tid  = threadIdx.x;
    const int warp = tid >> 5;
    const int lane = tid & 31;

    s_i[tid] = reinterpret_cast<const float4*>(i_feats + (size_t)b * D_DIM)[tid];
    __syncthreads();

    const int token = blockIdx.x * 8 + warp;
    if (token >= L) return;

    const float4* __restrict__ tok = reinterpret_cast<const float4*>(
        image_feats + ((size_t)b * L + token) * D_DIM) + lane;

    float dot = 0.f, nt2 = 0.f;
    #pragma unroll
    for (int j = 0; j < NVEC / 32; ++j) {             // 8 iterations
        float4 v = __ldg(tok + j * 32);               // coalesced 128B/warp/step
        float4 a = s_i[lane + j * 32];
        dot += a.x * v.x + a.y * v.y + a.z * v.z + a.w * v.w;
        nt2 += v.x * v.x + v.y * v.y + v.z * v.z + v.w * v.w;
    }

    #pragma unroll
    for (int off = 16; off > 0; off >>= 1) {
        dot += __shfl_xor_sync(0xffffffffu, dot, off);
        nt2 += __shfl_xor_sync(0xffffffffu, nt2, off);
    }

    if (lane == 0)
        g_sims[b * L + token] = dot * rsqrtf(fmaxf(nt2, 1e-16f));
}

// ---------------------------------------------------------------------------
// Kernel T: fused select + gather-mean tail.
// grid = (DSPLIT, B) = 1024 blocks, block = 256 threads.
// Each block independently recomputes the bottom-k selection from g_sims
// (rank-based, collision-free compaction, top_k-stable ties), then gathers
// its 64-float4 chunk of the selected rows:
//   thread = (token-group tg in [0,4), slot in [0,64)); tg sums tokens
//   tg, tg+4, ... (~6 independent coalesced loads), partials reduced in smem.
// ---------------------------------------------------------------------------
__global__ void __launch_bounds__(256)
select_gather_kernel(const float* __restrict__ image_feats,
                     const int* __restrict__ k_ptr,
                     float* __restrict__ out,
                     int L)
{
    __shared__ float  s_v[MAX_L];      // 2.3 KB sims
    __shared__ int    s_idx[MAX_K];
    __shared__ float4 s_part[256];     // 4 KB partials

    const int split = blockIdx.x;      // 0..3 : which 64-float4 chunk
    const int b     = blockIdx.y;
    const int tid   = threadIdx.x;

    int k = *k_ptr;
    if (k < 1) k = 1;
    if (k > MAX_K) k = MAX_K;

    // load sims (L2-hot: written by kernel A just before)
    for (int i = tid; i < L; i += 256)
        s_v[i] = g_sims[b * L + i];
    __syncthreads();

    // rank-based bottom-k: rank(i) = #{ j : v_j < v_i || (v_j==v_i && j<i) }
    for (int i = tid; i < L; i += 256) {
        const float v = s_v[i];
        int rank = 0;
        #pragma unroll 8
        for (int j = 0; j < MAX_L; ++j) {
            float w = s_v[j];                          // LDS broadcast
            rank += (w < v) | ((w == v) & (j < i));
        }
        if (rank < k)
            s_idx[rank] = i;
    }
    __syncthreads();

    // gather: tg = tid/64 in [0,4); slot = tid%64; global float4 slot:
    const int tg    = tid >> 6;
    const int slot  = tid & 63;
    const int gslot = split * 64 + slot;

    const float4* __restrict__ rowbase = reinterpret_cast<const float4*>(
        image_feats + (size_t)b * L * D_DIM);

    float4 acc = make_float4(0.f, 0.f, 0.f, 0.f);
    #pragma unroll 6
    for (int j = tg; j < k; j += 4) {
        float4 v = __ldg(rowbase + (size_t)s_idx[j] * NVEC + gslot);
        acc.x += v.x; acc.y += v.y; acc.z += v.z; acc.w += v.w;
    }
    s_part[tid] = acc;
    __syncthreads();

    if (tg == 0) {
        float4 a0 = s_part[slot];
        float4 a1 = s_part[64 + slot];
        float4 a2 = s_part[128 + slot];
        float4 a3 = s_part[192 + slot];
        const float inv_k = 1.0f / (float)k;
        float4 r;
        r.x = (a0.x + a1.x + a2.x + a3.x) * inv_k;
        r.y = (a0.y + a1.y + a2.y + a3.y) * inv_k;
        r.z = (a0.z + a1.z + a2.z + a3.z) * inv_k;
        r.w = (a0.w + a1.w + a2.w + a3.w) * inv_k;
        reinterpret_cast<float4*>(out + (size_t)b * D_DIM)[gslot] = r;
    }
}

// ---------------------------------------------------------------------------
extern "C" void kernel_launch(void* const* d_in, const int* in_sizes, int n_in,
                              void* d_out, int out_size)
{
    const float* i_feats     = (const float*)d_in[0];   // [B, D]
    const float* image_feats = (const float*)d_in[1];   // [B, L, D]
    const int*   k_ptr       = (const int*)d_in[2];     // scalar k

    const int B = in_sizes[0] / D_DIM;                  // 256
    const int L = in_sizes[1] / in_sizes[0];            // 576

    dim3 gridA((L + 7) / 8, B);
    sims_kernel<<<gridA, 256>>>(i_feats, image_feats, L);

    dim3 gridT(DSPLIT, B);
    select_gather_kernel<<<gridT, 256>>>(image_feats, k_ptr, (float*)d_out, L);
}